// round 14
// baseline (speedup 1.0000x reference)
#include <cuda_runtime.h>
#include <cstdint>
#include <math.h>

// ---------------------------------------------------------------------------
//   output  : float32 [64, 1000]       (64000 elems)
//   target  : int64/int32 [64]         (64 elems)
//   feats_a : float32 [3, 64, 65536]   (12582912 elems)
//   feats_b : float32 [4, 64, 32768]   (8388608 elems)
//   out     : float32 [base + 64000]   (loss..., logits passthrough)
// 2 launches: gram+ce (704 CTAs) -> tail (896 CTAs: reduce, gated pair+finalize)
// ---------------------------------------------------------------------------

#define NS      64
#define KT      64              // k-columns per smem stage
#define CHUNK   512             // D-columns per gram CTA
#define NIT     (CHUNK/KT)      // 8 stages
#define STRIDE  68              // smem row stride in words (68%32=4 -> conflict-free)
#define NSTG    3               // cp.async pipeline depth
#define CA      128             // chunks per feats_a feature (65536/512)
#define CB      64              // chunks per feats_b feature (32768/512)
#define NBLK    (3*CA + 4*CB)   // 640 gram CTAs
#define CEB     64
#define RBLK    896             // tail reduce CTAs (7 features x 128 groups)
#define TROLES  23              // 16 pair + 7 rowsum roles

__device__ float  g_partial[(size_t)NBLK * 4096];
__device__ double g_K[7 * 4096];
__device__ double g_rs[7 * 64];
__device__ double g_trkl[16];
__device__ double g_rowce[64];
__device__ int    g_ctr1;       // reduce-done counter (self-resetting)
__device__ int    g_ctr2;       // role-done counter   (self-resetting)

__device__ __constant__ int c_pi[16] = {0,0,0,1,1,2, 3,3,3,3,4,4,4,5,5,6};
__device__ __constant__ int c_pj[16] = {0,1,2,1,2,2, 3,4,5,6,4,5,6,5,6,6};

__device__ __forceinline__ void cp_async16(uint32_t s, const void* g) {
    asm volatile("cp.async.cg.shared.global [%0], [%1], 16;\n" :: "r"(s), "l"(g));
}
#define CP_COMMIT()  asm volatile("cp.async.commit_group;\n" ::: "memory")
#define CP_WAIT(n)   asm volatile("cp.async.wait_group %0;\n" :: "n"(n) : "memory")

__device__ __forceinline__ void mma_tf32(float c[4], const unsigned a[4], const unsigned b[2]) {
    asm volatile(
        "mma.sync.aligned.m16n8k8.row.col.f32.tf32.tf32.f32 "
        "{%0,%1,%2,%3}, {%4,%5,%6,%7}, {%8,%9}, {%0,%1,%2,%3};\n"
        : "+f"(c[0]), "+f"(c[1]), "+f"(c[2]), "+f"(c[3])
        : "r"(a[0]), "r"(a[1]), "r"(a[2]), "r"(a[3]), "r"(b[0]), "r"(b[1]));
}

// ---------------------------------------------------------------------------
// Kernel A: blocks [0,640): partial Grams, 3-stage cp.async pipeline
//           blocks [640,704): per-row log-softmax CE + logits passthrough
// ---------------------------------------------------------------------------
__global__ __launch_bounds__(128) void gram_ce(const float* __restrict__ fa,
                                               const float* __restrict__ fb,
                                               const float* __restrict__ logits,
                                               const void*  __restrict__ tgt_raw,
                                               float* __restrict__ out, int out_size) {
    const int bid = blockIdx.x;
    const int tid = threadIdx.x;
    const int lane = tid & 31, wid = tid >> 5;

    if (bid >= NBLK) {
        // ------------------ fused CE + copy ------------------
        __shared__ float  smx[4];
        __shared__ double sdx[4];
        const int row = bid - NBLK;
        const float* x = logits + row * 1000;

        float m = -1e30f;
        for (int cc = tid; cc < 1000; cc += 128) m = fmaxf(m, x[cc]);
#pragma unroll
        for (int o = 16; o; o >>= 1) m = fmaxf(m, __shfl_xor_sync(0xffffffffu, m, o));
        if (lane == 0) smx[wid] = m;
        __syncthreads();
        const float mv = fmaxf(fmaxf(smx[0], smx[1]), fmaxf(smx[2], smx[3]));

        double a = 0.0;
        for (int cc = tid; cc < 1000; cc += 128) a += (double)expf(x[cc] - mv);
#pragma unroll
        for (int o = 16; o; o >>= 1) a += __shfl_xor_sync(0xffffffffu, a, o);
        if (lane == 0) sdx[wid] = a;

        int ok = 1;
        if (tid < 64) {
            long long v = ((const long long*)tgt_raw)[tid];
            ok = (v >= 0 && v < 1000);
        }
        int is64 = __syncthreads_and(ok);

        if (tid == 0) {
            double tot = sdx[0] + sdx[1] + sdx[2] + sdx[3];
            long long tt = is64 ? ((const long long*)tgt_raw)[row]
                                : (long long)((const int*)tgt_raw)[row];
            if (tt < 0) tt = 0;
            if (tt > 999) tt = 999;
            g_rowce[row] = (double)x[tt] - (double)mv - log(tot);
        }

        int base = out_size - 64000;
        for (int cc = tid; cc < 1000; cc += 128) {
            int o = base + row * 1000 + cc;
            if (o >= 0 && o < out_size) out[o] = x[cc];
        }
        return;
    }

    // ------------------ gram CTA ------------------
    __shared__ unsigned tile[NSTG][64 * STRIDE];

    const float* X;
    int D, c0;
    if (bid < 3 * CA) {
        int f = bid / CA, ch = bid % CA;
        D = 65536; X = fa + (size_t)f * NS * D; c0 = ch * CHUNK;
    } else {
        int t = bid - 3 * CA;
        int f = t / CB, ch = t % CB;
        D = 32768; X = fb + (size_t)f * NS * D; c0 = ch * CHUNK;
    }

    const int g = lane >> 2, t4 = lane & 3;
    const int wm = wid >> 1, wn = wid & 1;

    uint32_t sbase;
    {
        unsigned long long t;
        asm("cvta.to.shared.u64 %0, %1;" : "=l"(t) : "l"((void*)tile));
        sbase = (uint32_t)t;
    }
    int r_[8], cq_[8];
#pragma unroll
    for (int j = 0; j < 8; j++) { int idx = tid + j * 128; r_[j] = idx >> 4; cq_[j] = idx & 15; }

    float c[2][4][4];
#pragma unroll
    for (int mi = 0; mi < 2; mi++)
#pragma unroll
        for (int ni = 0; ni < 4; ni++)
#pragma unroll
            for (int k = 0; k < 4; k++) c[mi][ni][k] = 0.f;

    auto PREFETCH = [&](int it) {
        const int gcol = c0 + it * KT;
        const uint32_t sb = sbase + (uint32_t)((it % NSTG) * 64 * STRIDE * 4);
#pragma unroll
        for (int j = 0; j < 8; j++)
            cp_async16(sb + (uint32_t)((r_[j] * STRIDE + cq_[j] * 4) * 4),
                       X + (size_t)r_[j] * D + gcol + cq_[j] * 4);
        CP_COMMIT();
    };

    PREFETCH(0);
    PREFETCH(1);
#pragma unroll
    for (int it = 0; it < NIT; ++it) {
        if (it + 1 < NIT) { CP_WAIT(1); } else { CP_WAIT(0); }
        __syncthreads();          // stage it%NSTG now valid for all warps
        const unsigned* buf = tile[it % NSTG];
#pragma unroll
        for (int ks = 0; ks < KT / 8; ++ks) {
            const int kc = ks * 8;
            unsigned a[2][4], b[4][2];
#pragma unroll
            for (int mi = 0; mi < 2; mi++) {
                int r0 = wm * 32 + mi * 16 + g;
                a[mi][0] = buf[r0 * STRIDE + kc + t4];
                a[mi][1] = buf[(r0 + 8) * STRIDE + kc + t4];
                a[mi][2] = buf[r0 * STRIDE + kc + t4 + 4];
                a[mi][3] = buf[(r0 + 8) * STRIDE + kc + t4 + 4];
            }
#pragma unroll
            for (int ni = 0; ni < 4; ni++) {
                int rn = wn * 32 + ni * 8 + g;
                b[ni][0] = buf[rn * STRIDE + kc + t4];
                b[ni][1] = buf[rn * STRIDE + kc + t4 + 4];
            }
#pragma unroll
            for (int mi = 0; mi < 2; mi++)
#pragma unroll
                for (int ni = 0; ni < 4; ni++)
                    mma_tf32(c[mi][ni], a[mi], b[ni]);
        }
        // prefetch stage (it+2): overwrites buffer (it-1)%NSTG, whose readers
        // all passed the barrier at the top of THIS iteration.
        if (it + 2 < NIT) PREFETCH(it + 2);
    }

    float* part = g_partial + (size_t)bid * 4096;
#pragma unroll
    for (int mi = 0; mi < 2; mi++)
#pragma unroll
        for (int ni = 0; ni < 4; ni++) {
            int R = wm * 32 + mi * 16 + g;
            int C = wn * 32 + ni * 8 + 2 * t4;
            part[R * 64 + C]           = c[mi][ni][0];
            part[R * 64 + C + 1]       = c[mi][ni][1];
            part[(R + 8) * 64 + C]     = c[mi][ni][2];
            part[(R + 8) * 64 + C + 1] = c[mi][ni][3];
        }
}

// ---------------------------------------------------------------------------
// Kernel B (tail): 896 CTAs.
// Phase 1 (all): reduce partials -> g_K (+diag zero). 7 features x 128 groups
//   of 32 entries; warp w sums chunks {w, w+16k} (compile-time unroll, MLP 8).
// Gate 1: last TROLES arrivers take roles; others exit.
//   role<16: tr(Ki Kj) dot (g_K is L2-hot).  role>=16: row sums of feature.
// Gate 2: last role CTA finalizes HSIC -> CKA -> loss, resets counters.
// ---------------------------------------------------------------------------
__global__ __launch_bounds__(512) void tail_kernel(float* __restrict__ out,
                                                   int out_size) {
    const int tid = threadIdx.x;
    const int wid = tid >> 5, lane = tid & 31;

    // ---------------- phase 1: reduce ----------------
    {
        const int cta  = blockIdx.x;
        const int f    = cta >> 7;
        const int gidx = cta & 127;
        const int e0   = gidx * 32;

        int base;
        bool big;
        if (f < 3) { base = f * CA;                big = true;  }
        else       { base = 3 * CA + (f - 3) * CB; big = false; }

        const float* p = g_partial + (size_t)base * 4096 + e0 + lane;

        double acc = 0.0;
        if (big) {
#pragma unroll
            for (int k = 0; k < 8; k++) acc += (double)p[(size_t)(wid + 16 * k) * 4096];
        } else {
#pragma unroll
            for (int k = 0; k < 4; k++) acc += (double)p[(size_t)(wid + 16 * k) * 4096];
        }

        __shared__ double s[16][32];
        s[wid][lane] = acc;
        __syncthreads();
        if (tid < 32) {
            double t = 0.0;
#pragma unroll
            for (int w2 = 0; w2 < 16; w2++) t += s[w2][tid];
            const int e = e0 + tid;
            if ((e >> 6) == (e & 63)) t = 0.0;
            g_K[f * 4096 + e] = t;
        }
    }

    __threadfence();
    __syncthreads();
    __shared__ int role_s;
    if (tid == 0) role_s = atomicAdd(&g_ctr1, 1) - (RBLK - TROLES);
    __syncthreads();
    const int role = role_s;
    if (role < 0) return;
    __threadfence();   // acquire: all g_K writes visible (ordered by the atomics)

    // ---------------- phase 2: pair dots / row sums ----------------
    if (role < 16) {
        const int p = role;
        const double* Ki = g_K + c_pi[p] * 4096;
        const double* Kj = g_K + c_pj[p] * 4096;
        double s = 0.0;
#pragma unroll
        for (int k = 0; k < 8; k++) s += Ki[tid + 512 * k] * Kj[tid + 512 * k];
#pragma unroll
        for (int o = 16; o; o >>= 1) s += __shfl_xor_sync(0xffffffffu, s, o);
        __shared__ double ws[16];
        if (lane == 0) ws[wid] = s;
        __syncthreads();
        if (wid == 0) {
            double v = (lane < 16) ? ws[lane] : 0.0;
#pragma unroll
            for (int o = 16; o; o >>= 1) v += __shfl_xor_sync(0xffffffffu, v, o);
            if (lane == 0) g_trkl[p] = v;
        }
    } else {
        const int f = role - 16;
        const double* Kf = g_K + f * 4096;
#pragma unroll
        for (int r = 0; r < 4; r++) {
            const int n = wid * 4 + r;
            double v = Kf[n * 64 + lane] + Kf[n * 64 + 32 + lane];
#pragma unroll
            for (int o = 16; o; o >>= 1) v += __shfl_xor_sync(0xffffffffu, v, o);
            if (lane == 0) g_rs[f * 64 + n] = v;
        }
    }

    __threadfence();
    __shared__ int last;
    if (tid == 0) last = (atomicAdd(&g_ctr2, 1) == TROLES - 1);
    __syncthreads();
    if (!last) return;
    __threadfence();

    // ---------------- phase 3: finalize ----------------
    __shared__ double rr_s[16], s_s[7], ce_w[2];
    if (tid < 16) {
        int i = c_pi[tid], j = c_pj[tid];
        double acc = 0.0;
        for (int n = 0; n < 64; n++) acc += g_rs[i * 64 + n] * g_rs[j * 64 + n];
        rr_s[tid] = acc;
    }
    if (tid >= 32 && tid < 39) {
        int f = tid - 32;
        double acc = 0.0;
        for (int n = 0; n < 64; n++) acc += g_rs[f * 64 + n];
        s_s[f] = acc;
    }
    if (tid >= 64 && tid < 128) {
        double cv = g_rowce[tid - 64];
#pragma unroll
        for (int o = 16; o; o >>= 1) cv += __shfl_xor_sync(0xffffffffu, cv, o);
        if (lane == 0) ce_w[wid - 2] = cv;
    }
    __syncthreads();

    if (tid == 0) {
        const double N = 64.0;
        double h[7][7];
        for (int q = 0; q < 16; q++) {
            int i = c_pi[q], j = c_pj[q];
            double hv = (g_trkl[q] + s_s[i] * s_s[j] / ((N - 1.0) * (N - 2.0))
                         - 2.0 * rr_s[q] / (N - 2.0)) / (N * (N - 3.0));
            h[i][j] = hv; h[j][i] = hv;
        }
        double d[7];
        for (int f = 0; f < 7; f++) d[f] = sqrt(h[f][f]);
        double cka = 0.0;
        for (int i = 0; i < 3; i++)
            for (int j = 0; j < 3; j++) cka += h[i][j] / (d[i] * d[j]);
        for (int i = 3; i < 7; i++)
            for (int j = 3; j < 7; j++) cka += h[i][j] / (d[i] * d[j]);
        double ce = -(ce_w[0] + ce_w[1]) / 64.0;
        float loss = (float)(ce + 0.1 * cka);
        int base = out_size - 64000;
        if (base < 1) base = (out_size > 0 ? 1 : 0);
        for (int k = 0; k < base && k < out_size; k++) out[k] = loss;
        g_ctr1 = 0;     // reset for next graph replay
        g_ctr2 = 0;
    }
}

// ---------------------------------------------------------------------------
extern "C" void kernel_launch(void* const* d_in, const int* in_sizes, int n_in,
                              void* d_out, int out_size) {
    const float* output = nullptr;
    const void*  target = nullptr;
    const float* fa     = nullptr;
    const float* fb     = nullptr;

    for (int i = 0; i < n_in; i++) {
        switch (in_sizes[i]) {
            case 64000:     output = (const float*)d_in[i]; break;
            case 64:        target = d_in[i];               break;
            case 12582912:  fa     = (const float*)d_in[i]; break;
            case 8388608:   fb     = (const float*)d_in[i]; break;
            default: break;
        }
    }
    float* out = (float*)d_out;
    if (!output || !target || !fa || !fb) {
        tail_kernel<<<RBLK, 512>>>(out, 0);
        return;
    }

    gram_ce<<<NBLK + CEB, 128>>>(fa, fb, output, target, out, out_size);
    tail_kernel<<<RBLK, 512>>>(out, out_size);
}

// round 15
// speedup vs baseline: 1.1281x; 1.1281x over previous
#include <cuda_runtime.h>
#include <cstdint>
#include <math.h>

// ---------------------------------------------------------------------------
//   output  : float32 [64, 1000]       (64000 elems)
//   target  : int64/int32 [64]         (64 elems)
//   feats_a : float32 [3, 64, 65536]   (12582912 elems)
//   feats_b : float32 [4, 64, 32768]   (8388608 elems)
//   out     : float32 [base + 64000]   (loss..., logits passthrough)
// 2 launches: gram+ce (704 CTAs) -> tail (896 CTAs: fp32 reduce, fp64 only at
// the 28K-entry boundary + pair/finalize).
// ---------------------------------------------------------------------------

#define NS      64
#define KT      64
#define CHUNK   512
#define NIT     (CHUNK/KT)      // 8 stages
#define STRIDE  68
#define NSTG    3
#define CA      128
#define CB      64
#define NBLK    (3*CA + 4*CB)   // 640 gram CTAs
#define CEB     64
#define RBLK    896             // tail CTAs (7 features x 128 groups)
#define TROLES  23              // 16 pair + 7 rowsum roles

__device__ float  g_partial[(size_t)NBLK * 4096];
__device__ double g_K[7 * 4096];
__device__ double g_rs[7 * 64];
__device__ double g_trkl[16];
__device__ double g_rowce[64];
__device__ int    g_ctr1;
__device__ int    g_ctr2;

__device__ __constant__ int c_pi[16] = {0,0,0,1,1,2, 3,3,3,3,4,4,4,5,5,6};
__device__ __constant__ int c_pj[16] = {0,1,2,1,2,2, 3,4,5,6,4,5,6,5,6,6};

__device__ __forceinline__ void cp_async16(uint32_t s, const void* g) {
    asm volatile("cp.async.cg.shared.global [%0], [%1], 16;\n" :: "r"(s), "l"(g));
}
#define CP_COMMIT()  asm volatile("cp.async.commit_group;\n" ::: "memory")
#define CP_WAIT(n)   asm volatile("cp.async.wait_group %0;\n" :: "n"(n) : "memory")

__device__ __forceinline__ void mma_tf32(float c[4], const unsigned a[4], const unsigned b[2]) {
    asm volatile(
        "mma.sync.aligned.m16n8k8.row.col.f32.tf32.tf32.f32 "
        "{%0,%1,%2,%3}, {%4,%5,%6,%7}, {%8,%9}, {%0,%1,%2,%3};\n"
        : "+f"(c[0]), "+f"(c[1]), "+f"(c[2]), "+f"(c[3])
        : "r"(a[0]), "r"(a[1]), "r"(a[2]), "r"(a[3]), "r"(b[0]), "r"(b[1]));
}

// ---------------------------------------------------------------------------
// Kernel A: blocks [0,640): partial Grams, 3-stage cp.async pipeline
//           blocks [640,704): per-row log-softmax CE + logits passthrough
// ---------------------------------------------------------------------------
__global__ __launch_bounds__(128) void gram_ce(const float* __restrict__ fa,
                                               const float* __restrict__ fb,
                                               const float* __restrict__ logits,
                                               const void*  __restrict__ tgt_raw,
                                               float* __restrict__ out, int out_size) {
    const int bid = blockIdx.x;
    const int tid = threadIdx.x;
    const int lane = tid & 31, wid = tid >> 5;

    if (bid >= NBLK) {
        // ------------------ fused CE + copy ------------------
        __shared__ float  smx[4];
        __shared__ double sdx[4];
        const int row = bid - NBLK;
        const float* x = logits + row * 1000;

        float m = -1e30f;
        for (int cc = tid; cc < 1000; cc += 128) m = fmaxf(m, x[cc]);
#pragma unroll
        for (int o = 16; o; o >>= 1) m = fmaxf(m, __shfl_xor_sync(0xffffffffu, m, o));
        if (lane == 0) smx[wid] = m;
        __syncthreads();
        const float mv = fmaxf(fmaxf(smx[0], smx[1]), fmaxf(smx[2], smx[3]));

        double a = 0.0;
        for (int cc = tid; cc < 1000; cc += 128) a += (double)expf(x[cc] - mv);
#pragma unroll
        for (int o = 16; o; o >>= 1) a += __shfl_xor_sync(0xffffffffu, a, o);
        if (lane == 0) sdx[wid] = a;

        int ok = 1;
        if (tid < 64) {
            long long v = ((const long long*)tgt_raw)[tid];
            ok = (v >= 0 && v < 1000);
        }
        int is64 = __syncthreads_and(ok);

        if (tid == 0) {
            double tot = sdx[0] + sdx[1] + sdx[2] + sdx[3];
            long long tt = is64 ? ((const long long*)tgt_raw)[row]
                                : (long long)((const int*)tgt_raw)[row];
            if (tt < 0) tt = 0;
            if (tt > 999) tt = 999;
            g_rowce[row] = (double)x[tt] - (double)mv - log(tot);
        }

        int base = out_size - 64000;
        for (int cc = tid; cc < 1000; cc += 128) {
            int o = base + row * 1000 + cc;
            if (o >= 0 && o < out_size) out[o] = x[cc];
        }
        return;
    }

    // ------------------ gram CTA ------------------
    __shared__ unsigned tile[NSTG][64 * STRIDE];

    const float* X;
    int D, c0;
    if (bid < 3 * CA) {
        int f = bid / CA, ch = bid % CA;
        D = 65536; X = fa + (size_t)f * NS * D; c0 = ch * CHUNK;
    } else {
        int t = bid - 3 * CA;
        int f = t / CB, ch = t % CB;
        D = 32768; X = fb + (size_t)f * NS * D; c0 = ch * CHUNK;
    }

    const int g = lane >> 2, t4 = lane & 3;
    const int wm = wid >> 1, wn = wid & 1;

    uint32_t sbase;
    {
        unsigned long long t;
        asm("cvta.to.shared.u64 %0, %1;" : "=l"(t) : "l"((void*)tile));
        sbase = (uint32_t)t;
    }
    int r_[8], cq_[8];
#pragma unroll
    for (int j = 0; j < 8; j++) { int idx = tid + j * 128; r_[j] = idx >> 4; cq_[j] = idx & 15; }

    float c[2][4][4];
#pragma unroll
    for (int mi = 0; mi < 2; mi++)
#pragma unroll
        for (int ni = 0; ni < 4; ni++)
#pragma unroll
            for (int k = 0; k < 4; k++) c[mi][ni][k] = 0.f;

    auto PREFETCH = [&](int it) {
        const int gcol = c0 + it * KT;
        const uint32_t sb = sbase + (uint32_t)((it % NSTG) * 64 * STRIDE * 4);
#pragma unroll
        for (int j = 0; j < 8; j++)
            cp_async16(sb + (uint32_t)((r_[j] * STRIDE + cq_[j] * 4) * 4),
                       X + (size_t)r_[j] * D + gcol + cq_[j] * 4);
        CP_COMMIT();
    };

    PREFETCH(0);
    PREFETCH(1);
#pragma unroll
    for (int it = 0; it < NIT; ++it) {
        if (it + 1 < NIT) { CP_WAIT(1); } else { CP_WAIT(0); }
        __syncthreads();
        const unsigned* buf = tile[it % NSTG];
#pragma unroll
        for (int ks = 0; ks < KT / 8; ++ks) {
            const int kc = ks * 8;
            unsigned a[2][4], b[4][2];
#pragma unroll
            for (int mi = 0; mi < 2; mi++) {
                int r0 = wm * 32 + mi * 16 + g;
                a[mi][0] = buf[r0 * STRIDE + kc + t4];
                a[mi][1] = buf[(r0 + 8) * STRIDE + kc + t4];
                a[mi][2] = buf[r0 * STRIDE + kc + t4 + 4];
                a[mi][3] = buf[(r0 + 8) * STRIDE + kc + t4 + 4];
            }
#pragma unroll
            for (int ni = 0; ni < 4; ni++) {
                int rn = wn * 32 + ni * 8 + g;
                b[ni][0] = buf[rn * STRIDE + kc + t4];
                b[ni][1] = buf[rn * STRIDE + kc + t4 + 4];
            }
#pragma unroll
            for (int mi = 0; mi < 2; mi++)
#pragma unroll
                for (int ni = 0; ni < 4; ni++)
                    mma_tf32(c[mi][ni], a[mi], b[ni]);
        }
        if (it + 2 < NIT) PREFETCH(it + 2);
    }

    float* part = g_partial + (size_t)bid * 4096;
#pragma unroll
    for (int mi = 0; mi < 2; mi++)
#pragma unroll
        for (int ni = 0; ni < 4; ni++) {
            int R = wm * 32 + mi * 16 + g;
            int C = wn * 32 + ni * 8 + 2 * t4;
            part[R * 64 + C]           = c[mi][ni][0];
            part[R * 64 + C + 1]       = c[mi][ni][1];
            part[(R + 8) * 64 + C]     = c[mi][ni][2];
            part[(R + 8) * 64 + C + 1] = c[mi][ni][3];
        }
}

// ---------------------------------------------------------------------------
// Kernel B (tail): 896 CTAs.
// Phase 1 (all): FP32 tree-reduce partials -> g_K (single f64 cvt per entry).
// Gate 1: last TROLES arrivers take roles (others exit):
//   role<16: tr(Ki Kj) fp64 dot (L2-hot).  role>=16: fp64 row sums.
// Gate 2: last role CTA finalizes HSIC -> CKA -> loss, resets counters.
// ---------------------------------------------------------------------------
__global__ __launch_bounds__(512) void tail_kernel(float* __restrict__ out,
                                                   int out_size) {
    const int tid = threadIdx.x;
    const int wid = tid >> 5, lane = tid & 31;

    // ---------------- phase 1: fp32 reduce ----------------
    {
        const int cta  = blockIdx.x;
        const int f    = cta >> 7;
        const int gidx = cta & 127;
        const int e0   = gidx * 32;

        int base;
        bool big;
        if (f < 3) { base = f * CA;                big = true;  }
        else       { base = 3 * CA + (f - 3) * CB; big = false; }

        const float* p = g_partial + (size_t)base * 4096 + e0 + lane;

        float acc;
        if (big) {
            float v[8];
#pragma unroll
            for (int k = 0; k < 8; k++) v[k] = p[(size_t)(wid + 16 * k) * 4096];
            acc = ((v[0] + v[1]) + (v[2] + v[3])) + ((v[4] + v[5]) + (v[6] + v[7]));
        } else {
            float v[4];
#pragma unroll
            for (int k = 0; k < 4; k++) v[k] = p[(size_t)(wid + 16 * k) * 4096];
            acc = (v[0] + v[1]) + (v[2] + v[3]);
        }

        __shared__ float s[16][33];
        s[wid][lane] = acc;
        __syncthreads();
        if (tid < 32) {
            float t0 = 0.f, t1 = 0.f, t2 = 0.f, t3 = 0.f;
#pragma unroll
            for (int w2 = 0; w2 < 16; w2 += 4) {
                t0 += s[w2 + 0][tid];
                t1 += s[w2 + 1][tid];
                t2 += s[w2 + 2][tid];
                t3 += s[w2 + 3][tid];
            }
            float t = (t0 + t1) + (t2 + t3);
            const int e = e0 + tid;
            g_K[f * 4096 + e] = ((e >> 6) == (e & 63)) ? 0.0 : (double)t;
        }
    }

    __threadfence();
    __syncthreads();
    __shared__ int role_s;
    if (tid == 0) role_s = atomicAdd(&g_ctr1, 1) - (RBLK - TROLES);
    __syncthreads();
    const int role = role_s;
    if (role < 0) return;
    __threadfence();   // acquire: all g_K writes visible

    // ---------------- phase 2: pair dots / row sums (fp64, tiny) ----------------
    if (role < 16) {
        const int p = role;
        const double* Ki = g_K + c_pi[p] * 4096;
        const double* Kj = g_K + c_pj[p] * 4096;
        double s = 0.0;
#pragma unroll
        for (int k = 0; k < 8; k++) s += Ki[tid + 512 * k] * Kj[tid + 512 * k];
#pragma unroll
        for (int o = 16; o; o >>= 1) s += __shfl_xor_sync(0xffffffffu, s, o);
        __shared__ double ws[16];
        if (lane == 0) ws[wid] = s;
        __syncthreads();
        if (wid == 0) {
            double v = (lane < 16) ? ws[lane] : 0.0;
#pragma unroll
            for (int o = 16; o; o >>= 1) v += __shfl_xor_sync(0xffffffffu, v, o);
            if (lane == 0) g_trkl[p] = v;
        }
    } else {
        const int f = role - 16;
        const double* Kf = g_K + f * 4096;
#pragma unroll
        for (int r = 0; r < 4; r++) {
            const int n = wid * 4 + r;
            double v = Kf[n * 64 + lane] + Kf[n * 64 + 32 + lane];
#pragma unroll
            for (int o = 16; o; o >>= 1) v += __shfl_xor_sync(0xffffffffu, v, o);
            if (lane == 0) g_rs[f * 64 + n] = v;
        }
    }

    __threadfence();
    __shared__ int last;
    if (tid == 0) last = (atomicAdd(&g_ctr2, 1) == TROLES - 1);
    __syncthreads();
    if (!last) return;
    __threadfence();

    // ---------------- phase 3: finalize ----------------
    __shared__ double rr_s[16], s_s[7], ce_w[2];
    if (tid < 16) {
        int i = c_pi[tid], j = c_pj[tid];
        double acc = 0.0;
        for (int n = 0; n < 64; n++) acc += g_rs[i * 64 + n] * g_rs[j * 64 + n];
        rr_s[tid] = acc;
    }
    if (tid >= 32 && tid < 39) {
        int f = tid - 32;
        double acc = 0.0;
        for (int n = 0; n < 64; n++) acc += g_rs[f * 64 + n];
        s_s[f] = acc;
    }
    if (tid >= 64 && tid < 128) {
        double cv = g_rowce[tid - 64];
#pragma unroll
        for (int o = 16; o; o >>= 1) cv += __shfl_xor_sync(0xffffffffu, cv, o);
        if (lane == 0) ce_w[wid - 2] = cv;
    }
    __syncthreads();

    if (tid == 0) {
        const double N = 64.0;
        double h[7][7];
        for (int q = 0; q < 16; q++) {
            int i = c_pi[q], j = c_pj[q];
            double hv = (g_trkl[q] + s_s[i] * s_s[j] / ((N - 1.0) * (N - 2.0))
                         - 2.0 * rr_s[q] / (N - 2.0)) / (N * (N - 3.0));
            h[i][j] = hv; h[j][i] = hv;
        }
        double d[7];
        for (int f = 0; f < 7; f++) d[f] = sqrt(h[f][f]);
        double cka = 0.0;
        for (int i = 0; i < 3; i++)
            for (int j = 0; j < 3; j++) cka += h[i][j] / (d[i] * d[j]);
        for (int i = 3; i < 7; i++)
            for (int j = 3; j < 7; j++) cka += h[i][j] / (d[i] * d[j]);
        double ce = -(ce_w[0] + ce_w[1]) / 64.0;
        float loss = (float)(ce + 0.1 * cka);
        int base = out_size - 64000;
        if (base < 1) base = (out_size > 0 ? 1 : 0);
        for (int k = 0; k < base && k < out_size; k++) out[k] = loss;
        g_ctr1 = 0;
        g_ctr2 = 0;
    }
}

// ---------------------------------------------------------------------------
extern "C" void kernel_launch(void* const* d_in, const int* in_sizes, int n_in,
                              void* d_out, int out_size) {
    const float* output = nullptr;
    const void*  target = nullptr;
    const float* fa     = nullptr;
    const float* fb     = nullptr;

    for (int i = 0; i < n_in; i++) {
        switch (in_sizes[i]) {
            case 64000:     output = (const float*)d_in[i]; break;
            case 64:        target = d_in[i];               break;
            case 12582912:  fa     = (const float*)d_in[i]; break;
            case 8388608:   fb     = (const float*)d_in[i]; break;
            default: break;
        }
    }
    float* out = (float*)d_out;
    if (!output || !target || !fa || !fb) {
        tail_kernel<<<RBLK, 512>>>(out, 0);
        return;
    }

    gram_ce<<<NBLK + CEB, 128>>>(fa, fb, output, target, out, out_size);
    tail_kernel<<<RBLK, 512>>>(out, out_size);
}

// round 17
// speedup vs baseline: 1.1636x; 1.0315x over previous
#include <cuda_runtime.h>
#include <cstdint>
#include <math.h>

// ---------------------------------------------------------------------------
//   output  : float32 [64, 1000]       (64000 elems)
//   target  : int64/int32 [64]         (64 elems)
//   feats_a : float32 [3, 64, 65536]   (12582912 elems)
//   feats_b : float32 [4, 64, 32768]   (8388608 elems)
//   out     : float32 [base + 64000]   (loss..., logits passthrough)
// SINGLE kernel, 704 CTAs:
//   [0,640):  gram tiles -> RED.F32 atomic accumulate into g_K32[feature]
//   [640,704): CE log-softmax + logits passthrough
//   counter gate: last 23 arrivers -> pair dots / row sums (diag masked);
//   last of those -> finalize HSIC->CKA->loss, re-zero g_K32 + counters.
// ---------------------------------------------------------------------------

#define NS      64
#define KT      64
#define CHUNK   512
#define NIT     (CHUNK/KT)      // 8 stages
#define STRIDE  68
#define NSTG    3
#define CA      128             // chunks per feats_a feature
#define CB      64              // chunks per feats_b feature
#define NBLK    (3*CA + 4*CB)   // 640 gram CTAs
#define CEB     64
#define TOTB    (NBLK + CEB)    // 704 CTAs
#define TROLES  23              // 16 pair + 7 rowsum roles

__device__ float  g_K32[7 * 4096];   // atomic fp32 Gram accumulators (self-zeroed)
__device__ double g_rs[7 * 64];
__device__ double g_trkl[16];
__device__ double g_rowce[64];
__device__ int    g_ctr1;            // CTA-done counter (self-resetting)
__device__ int    g_ctr2;            // role-done counter (self-resetting)

__device__ __constant__ int c_pi[16] = {0,0,0,1,1,2, 3,3,3,3,4,4,4,5,5,6};
__device__ __constant__ int c_pj[16] = {0,1,2,1,2,2, 3,4,5,6,4,5,6,5,6,6};

__device__ __forceinline__ void cp_async16(uint32_t s, const void* g) {
    asm volatile("cp.async.cg.shared.global [%0], [%1], 16;\n" :: "r"(s), "l"(g));
}
#define CP_COMMIT()  asm volatile("cp.async.commit_group;\n" ::: "memory")
#define CP_WAIT(n)   asm volatile("cp.async.wait_group %0;\n" :: "n"(n) : "memory")

__device__ __forceinline__ void mma_tf32(float c[4], const unsigned a[4], const unsigned b[2]) {
    asm volatile(
        "mma.sync.aligned.m16n8k8.row.col.f32.tf32.tf32.f32 "
        "{%0,%1,%2,%3}, {%4,%5,%6,%7}, {%8,%9}, {%0,%1,%2,%3};\n"
        : "+f"(c[0]), "+f"(c[1]), "+f"(c[2]), "+f"(c[3])
        : "r"(a[0]), "r"(a[1]), "r"(a[2]), "r"(a[3]), "r"(b[0]), "r"(b[1]));
}

// red.global.add.f32 — fire-and-forget (no return value, REDG pipe)
__device__ __forceinline__ void red_add_f32(float* addr, float v) {
    asm volatile("red.global.add.f32 [%0], %1;\n" :: "l"(addr), "f"(v) : "memory");
}

__global__ __launch_bounds__(128) void fused_kernel(const float* __restrict__ fa,
                                                    const float* __restrict__ fb,
                                                    const float* __restrict__ logits,
                                                    const void*  __restrict__ tgt_raw,
                                                    float* __restrict__ out, int out_size) {
    const int bid = blockIdx.x;
    const int tid = threadIdx.x;
    const int lane = tid & 31, wid = tid >> 5;

    if (bid >= NBLK) {
        // ================= CE + logits passthrough =================
        __shared__ float  smx[4];
        __shared__ double sdx[4];
        const int row = bid - NBLK;
        const float* x = logits + row * 1000;

        float m = -1e30f;
        for (int cc = tid; cc < 1000; cc += 128) m = fmaxf(m, x[cc]);
#pragma unroll
        for (int o = 16; o; o >>= 1) m = fmaxf(m, __shfl_xor_sync(0xffffffffu, m, o));
        if (lane == 0) smx[wid] = m;
        __syncthreads();
        const float mv = fmaxf(fmaxf(smx[0], smx[1]), fmaxf(smx[2], smx[3]));

        double a = 0.0;
        for (int cc = tid; cc < 1000; cc += 128) a += (double)expf(x[cc] - mv);
#pragma unroll
        for (int o = 16; o; o >>= 1) a += __shfl_xor_sync(0xffffffffu, a, o);
        if (lane == 0) sdx[wid] = a;

        int ok = 1;
        if (tid < 64) {
            long long v = ((const long long*)tgt_raw)[tid];
            ok = (v >= 0 && v < 1000);
        }
        int is64 = __syncthreads_and(ok);

        if (tid == 0) {
            double tot = sdx[0] + sdx[1] + sdx[2] + sdx[3];
            long long tt = is64 ? ((const long long*)tgt_raw)[row]
                                : (long long)((const int*)tgt_raw)[row];
            if (tt < 0) tt = 0;
            if (tt > 999) tt = 999;
            g_rowce[row] = (double)x[tt] - (double)mv - log(tot);
        }

        int obase = out_size - 64000;
        for (int cc = tid; cc < 1000; cc += 128) {
            int o = obase + row * 1000 + cc;
            if (o >= 0 && o < out_size) out[o] = x[cc];
        }
    } else {
        // ================= gram tile =================
        __shared__ unsigned tile[NSTG][64 * STRIDE];

        const float* X;
        int D, c0, ff;
        if (bid < 3 * CA) {
            ff = bid / CA;
            int ch = bid % CA;
            D = 65536; X = fa + (size_t)ff * NS * D; c0 = ch * CHUNK;
        } else {
            int t = bid - 3 * CA;
            ff = 3 + t / CB;
            int ch = t % CB;
            D = 32768; X = fb + (size_t)(ff - 3) * NS * D; c0 = ch * CHUNK;
        }

        const int g = lane >> 2, t4 = lane & 3;
        const int wm = wid >> 1, wn = wid & 1;

        uint32_t sbase;
        {
            unsigned long long t;
            asm("cvta.to.shared.u64 %0, %1;" : "=l"(t) : "l"((void*)tile));
            sbase = (uint32_t)t;
        }
        int r_[8], cq_[8];
#pragma unroll
        for (int j = 0; j < 8; j++) { int idx = tid + j * 128; r_[j] = idx >> 4; cq_[j] = idx & 15; }

        float c[2][4][4];
#pragma unroll
        for (int mi = 0; mi < 2; mi++)
#pragma unroll
            for (int ni = 0; ni < 4; ni++)
#pragma unroll
                for (int k = 0; k < 4; k++) c[mi][ni][k] = 0.f;

        auto PREFETCH = [&](int it) {
            const int gcol = c0 + it * KT;
            const uint32_t sb = sbase + (uint32_t)((it % NSTG) * 64 * STRIDE * 4);
#pragma unroll
            for (int j = 0; j < 8; j++)
                cp_async16(sb + (uint32_t)((r_[j] * STRIDE + cq_[j] * 4) * 4),
                           X + (size_t)r_[j] * D + gcol + cq_[j] * 4);
            CP_COMMIT();
        };

        PREFETCH(0);
        PREFETCH(1);
#pragma unroll
        for (int it = 0; it < NIT; ++it) {
            if (it + 1 < NIT) { CP_WAIT(1); } else { CP_WAIT(0); }
            __syncthreads();
            const unsigned* buf = tile[it % NSTG];
#pragma unroll
            for (int ks = 0; ks < KT / 8; ++ks) {
                const int kc = ks * 8;
                unsigned a[2][4], b[4][2];
#pragma unroll
                for (int mi = 0; mi < 2; mi++) {
                    int r0 = wm * 32 + mi * 16 + g;
                    a[mi][0] = buf[r0 * STRIDE + kc + t4];
                    a[mi][1] = buf[(r0 + 8) * STRIDE + kc + t4];
                    a[mi][2] = buf[r0 * STRIDE + kc + t4 + 4];
                    a[mi][3] = buf[(r0 + 8) * STRIDE + kc + t4 + 4];
                }
#pragma unroll
                for (int ni = 0; ni < 4; ni++) {
                    int rn = wn * 32 + ni * 8 + g;
                    b[ni][0] = buf[rn * STRIDE + kc + t4];
                    b[ni][1] = buf[rn * STRIDE + kc + t4 + 4];
                }
#pragma unroll
                for (int mi = 0; mi < 2; mi++)
#pragma unroll
                    for (int ni = 0; ni < 4; ni++)
                        mma_tf32(c[mi][ni], a[mi], b[ni]);
            }
            if (it + 2 < NIT) PREFETCH(it + 2);
        }

        // epilogue: atomic-accumulate partial Gram into g_K32[ff]
        float* Kf = g_K32 + ff * 4096;
#pragma unroll
        for (int mi = 0; mi < 2; mi++)
#pragma unroll
            for (int ni = 0; ni < 4; ni++) {
                int R = wm * 32 + mi * 16 + g;
                int C = wn * 32 + ni * 8 + 2 * t4;
                red_add_f32(Kf + R * 64 + C,           c[mi][ni][0]);
                red_add_f32(Kf + R * 64 + C + 1,       c[mi][ni][1]);
                red_add_f32(Kf + (R + 8) * 64 + C,     c[mi][ni][2]);
                red_add_f32(Kf + (R + 8) * 64 + C + 1, c[mi][ni][3]);
            }
    }

    // ================= gate 1: last TROLES CTAs take tail roles =================
    __threadfence();
    __syncthreads();
    __shared__ int role_s;
    if (tid == 0) role_s = atomicAdd(&g_ctr1, 1) - (TOTB - TROLES);
    __syncthreads();
    const int role = role_s;
    if (role < 0) return;
    __threadfence();   // acquire: all REDs / g_rowce visible

    // ================= phase 2: pair dots / row sums (128 threads) =============
    if (role < 16) {
        const int p = role;
        const float* Ki = g_K32 + c_pi[p] * 4096;
        const float* Kj = g_K32 + c_pj[p] * 4096;
        double s = 0.0;
#pragma unroll
        for (int k = 0; k < 32; k++) {
            const int e = tid + 128 * k;
            if ((e >> 6) != (e & 63))            // mask diagonal
                s += (double)__ldcg(Ki + e) * (double)__ldcg(Kj + e);
        }
#pragma unroll
        for (int o = 16; o; o >>= 1) s += __shfl_xor_sync(0xffffffffu, s, o);
        __shared__ double ws[4];
        if (lane == 0) ws[wid] = s;
        __syncthreads();
        if (tid == 0) g_trkl[p] = (ws[0] + ws[1]) + (ws[2] + ws[3]);
    } else {
        const int f = role - 16;
        const float* Kf = g_K32 + f * 4096;
#pragma unroll
        for (int r = 0; r < 16; r++) {
            const int n = wid * 16 + r;
            double v = 0.0;
            if (lane != n)        v += (double)__ldcg(Kf + n * 64 + lane);
            if ((lane + 32) != n) v += (double)__ldcg(Kf + n * 64 + 32 + lane);
#pragma unroll
            for (int o = 16; o; o >>= 1) v += __shfl_xor_sync(0xffffffffu, v, o);
            if (lane == 0) g_rs[f * 64 + n] = v;
        }
    }

    __threadfence();
    __shared__ int last;
    if (tid == 0) last = (atomicAdd(&g_ctr2, 1) == TROLES - 1);
    __syncthreads();
    if (!last) return;
    __threadfence();

    // ================= phase 3: finalize =================
    __shared__ double rr_s[16], s_s[7], ce_w[2];
    if (tid < 16) {
        int i = c_pi[tid], j = c_pj[tid];
        double acc = 0.0;
        for (int n = 0; n < 64; n++) acc += g_rs[i * 64 + n] * g_rs[j * 64 + n];
        rr_s[tid] = acc;
    }
    if (tid >= 32 && tid < 39) {
        int f = tid - 32;
        double acc = 0.0;
        for (int n = 0; n < 64; n++) acc += g_rs[f * 64 + n];
        s_s[f] = acc;
    }
    if (tid >= 64 && tid < 128) {
        double cv = g_rowce[tid - 64];
#pragma unroll
        for (int o = 16; o; o >>= 1) cv += __shfl_xor_sync(0xffffffffu, cv, o);
        if (lane == 0) ce_w[wid - 2] = cv;
    }
    __syncthreads();

    if (tid == 0) {
        const double N = 64.0;
        double h[7][7];
        for (int q = 0; q < 16; q++) {
            int i = c_pi[q], j = c_pj[q];
            double hv = (g_trkl[q] + s_s[i] * s_s[j] / ((N - 1.0) * (N - 2.0))
                         - 2.0 * rr_s[q] / (N - 2.0)) / (N * (N - 3.0));
            h[i][j] = hv; h[j][i] = hv;
        }
        double d[7];
        for (int f = 0; f < 7; f++) d[f] = sqrt(h[f][f]);
        double cka = 0.0;
        for (int i = 0; i < 3; i++)
            for (int j = 0; j < 3; j++) cka += h[i][j] / (d[i] * d[j]);
        for (int i = 3; i < 7; i++)
            for (int j = 3; j < 7; j++) cka += h[i][j] / (d[i] * d[j]);
        double ce = -(ce_w[0] + ce_w[1]) / 64.0;
        float loss = (float)(ce + 0.1 * cka);
        int obase = out_size - 64000;
        if (obase < 1) obase = (out_size > 0 ? 1 : 0);
        for (int k = 0; k < obase && k < out_size; k++) out[k] = loss;
    }

    // re-zero accumulators + counters for next graph replay
    {
        float4 z = {0.f, 0.f, 0.f, 0.f};
        float4* K4 = reinterpret_cast<float4*>(g_K32);
        for (int i = tid; i < 7 * 1024; i += 128) K4[i] = z;
    }
    __syncthreads();
    if (tid == 0) { g_ctr1 = 0; g_ctr2 = 0; }
}

// ---------------------------------------------------------------------------
extern "C" void kernel_launch(void* const* d_in, const int* in_sizes, int n_in,
                              void* d_out, int out_size) {
    const float* output = nullptr;
    const void*  target = nullptr;
    const float* fa     = nullptr;
    const float* fb     = nullptr;

    for (int i = 0; i < n_in; i++) {
        switch (in_sizes[i]) {
            case 64000:     output = (const float*)d_in[i]; break;
            case 64:        target = d_in[i];               break;
            case 12582912:  fa     = (const float*)d_in[i]; break;
            case 8388608:   fb     = (const float*)d_in[i]; break;
            default: break;
        }
    }
    float* out = (float*)d_out;
    if (!output || !target || !fa || !fb) return;

    fused_kernel<<<TOTB, 128>>>(fa, fb, output, target, out, out_size);
}